// round 2
// baseline (speedup 1.0000x reference)
#include <cuda_runtime.h>

// Problem constants
#define BB 16
#define TT 4096
#define DD 768
#define NBOX 1024
#define MAXB 128
#define DDETR 256
#define VIS_ELEMS (BB*MAXB*DD)   // 1,572,864
#define MASK_ELEMS (BB*MAXB)     // 2,048
#define NC 64                    // t-chunks for mean reduction

// ---------------- scratch (device globals; no allocations allowed) ----------
__device__ __align__(16) float g_partial[BB*NC*DD];
__device__ __align__(16) float g_x[BB*DD];
__device__ __align__(16) float g_h1t[BB*DD];
__device__ __align__(16) float g_h1d[BB*DD];
__device__ __align__(16) float g_xt[BB*DD];
__device__ __align__(16) float g_fm1[NBOX*DD];
__device__ __align__(16) float g_fm[NBOX*DD];
__device__ int g_pos[NBOX];

// ---------------- tf32 helpers ----------------------------------------------
__device__ __forceinline__ unsigned f2tf(float x) {
    unsigned r;
    asm("cvt.rna.tf32.f32 %0, %1;" : "=r"(r) : "f"(x));
    return r;
}
__device__ __forceinline__ void split_tf32(float x, unsigned& hi, unsigned& lo) {
    hi = f2tf(x);
    lo = f2tf(x - __uint_as_float(hi));
}
__device__ __forceinline__ void mma_tf32(float* c,
                                         unsigned a0, unsigned a1, unsigned a2, unsigned a3,
                                         unsigned b0, unsigned b1) {
    asm("mma.sync.aligned.m16n8k8.row.col.f32.tf32.tf32.f32 "
        "{%0,%1,%2,%3}, {%4,%5,%6,%7}, {%8,%9}, {%0,%1,%2,%3};"
        : "+f"(c[0]), "+f"(c[1]), "+f"(c[2]), "+f"(c[3])
        : "r"(a0), "r"(a1), "r"(a2), "r"(a3), "r"(b0), "r"(b1));
}

// One BK=32 k-tile of 3xTF32 MMAs. Block tile 64x64, 4 warps of 32x32.
// smem layout: [k][row/col] padded to 68 (68%32==4 -> conflict-free frags).
__device__ __forceinline__ void mma_ktile(
    const unsigned Ah[32][68], const unsigned Al[32][68],
    const unsigned Bh[32][68], const unsigned Bl[32][68],
    int wm, int wn, int gid, int tig, float c[2][4][4])
{
#pragma unroll
    for (int ks = 0; ks < 4; ks++) {
        const int k0 = ks * 8;
        unsigned ah[2][4], al[2][4];
#pragma unroll
        for (int mt = 0; mt < 2; mt++) {
            int r = wm * 32 + mt * 16 + gid;
            ah[mt][0] = Ah[k0 + tig][r];     ah[mt][1] = Ah[k0 + tig][r + 8];
            ah[mt][2] = Ah[k0 + tig + 4][r]; ah[mt][3] = Ah[k0 + tig + 4][r + 8];
            al[mt][0] = Al[k0 + tig][r];     al[mt][1] = Al[k0 + tig][r + 8];
            al[mt][2] = Al[k0 + tig + 4][r]; al[mt][3] = Al[k0 + tig + 4][r + 8];
        }
#pragma unroll
        for (int nt = 0; nt < 4; nt++) {
            int cn = wn * 32 + nt * 8 + gid;
            unsigned bh0 = Bh[k0 + tig][cn], bh1 = Bh[k0 + tig + 4][cn];
            unsigned bl0 = Bl[k0 + tig][cn], bl1 = Bl[k0 + tig + 4][cn];
#pragma unroll
            for (int mt = 0; mt < 2; mt++) {
                mma_tf32(c[mt][nt], ah[mt][0], ah[mt][1], ah[mt][2], ah[mt][3], bl0, bl1);
                mma_tf32(c[mt][nt], al[mt][0], al[mt][1], al[mt][2], al[mt][3], bh0, bh1);
                mma_tf32(c[mt][nt], ah[mt][0], ah[mt][1], ah[mt][2], ah[mt][3], bh0, bh1);
            }
        }
    }
}

// float4 tile loader: 64 rows x 32 k from row-major src, split to hi/lo smem.
__device__ __forceinline__ void load_tile_f4(const float* __restrict__ src, int stride,
                                             int row0, int k0,
                                             unsigned Sh[32][68], unsigned Sl[32][68],
                                             int tid) {
#pragma unroll
    for (int i = 0; i < 4; i++) {
        int f = tid + i * 128;
        int r = f >> 3, c4 = (f & 7) * 4;
        float4 v = *reinterpret_cast<const float4*>(src + (size_t)(row0 + r) * stride + k0 + c4);
        split_tf32(v.x, Sh[c4 + 0][r], Sl[c4 + 0][r]);
        split_tf32(v.y, Sh[c4 + 1][r], Sl[c4 + 1][r]);
        split_tf32(v.z, Sh[c4 + 2][r], Sl[c4 + 2][r]);
        split_tf32(v.w, Sh[c4 + 3][r], Sl[c4 + 3][r]);
    }
}

// ---------------- zero vis_output region ------------------------------------
__global__ void zero_vis_kernel(float4* __restrict__ out) {
    const int n4 = VIS_ELEMS / 4;
    for (int i = blockIdx.x * blockDim.x + threadIdx.x; i < n4;
         i += gridDim.x * blockDim.x)
        out[i] = make_float4(0.f, 0.f, 0.f, 0.f);
}

// ---------------- mean over T: pass 1 ---------------------------------------
__global__ void mean_partial_kernel(const float* __restrict__ in) {
    int b = blockIdx.x >> 6;
    int c = blockIdx.x & 63;
    const float4* p = reinterpret_cast<const float4*>(
        in + ((size_t)b * TT + (size_t)c * 64) * DD) + threadIdx.x;
    float4 acc = make_float4(0.f, 0.f, 0.f, 0.f);
    #pragma unroll 8
    for (int r = 0; r < 64; r++) {
        float4 v = p[(size_t)r * (DD / 4)];
        acc.x += v.x; acc.y += v.y; acc.z += v.z; acc.w += v.w;
    }
    reinterpret_cast<float4*>(g_partial + ((size_t)b * NC + c) * DD)[threadIdx.x] = acc;
}

// ---------------- mean over T: pass 2 ---------------------------------------
__global__ void mean_final_kernel() {
    int i = blockIdx.x * blockDim.x + threadIdx.x;
    int b  = i / (DD / 4);
    int c4 = i % (DD / 4);
    const float4* p = reinterpret_cast<const float4*>(g_partial)
                      + (size_t)b * NC * (DD / 4) + c4;
    float4 acc = make_float4(0.f, 0.f, 0.f, 0.f);
    #pragma unroll 8
    for (int c = 0; c < NC; c++) {
        float4 v = p[(size_t)c * (DD / 4)];
        acc.x += v.x; acc.y += v.y; acc.z += v.z; acc.w += v.w;
    }
    const float s = 1.0f / (float)TT;
    acc.x *= s; acc.y *= s; acc.z *= s; acc.w *= s;
    reinterpret_cast<float4*>(g_x)[(size_t)b * (DD / 4) + c4] = acc;
}

// ---------------- small MLP (no smem staging; x is L1/L2-resident) ----------
// grid = 192 blocks (96/branch), 256 thr (8 warps, 1 warp = 1 output column)
__global__ __launch_bounds__(256) void small_mlp_kernel(int layer,
        const float* __restrict__ w0, const float* __restrict__ b0,
        const float* __restrict__ w1, const float* __restrict__ b1,
        float* __restrict__ retx_out) {
    int branch = blockIdx.x / 96;
    const float* in   = (layer == 0) ? g_x : (branch ? g_h1d : g_h1t);
    const float* w    = branch ? w1 : w0;
    const float* bias = branch ? b1 : b0;
    float* out        = (layer == 0) ? (branch ? g_h1d : g_h1t)
                                     : (branch ? retx_out : g_xt);
    int warp = threadIdx.x >> 5, lane = threadIdx.x & 31;
    int j = (blockIdx.x % 96) * 8 + warp;
    const float* wr = w + (size_t)j * DD;
    float acc[BB];
#pragma unroll
    for (int b = 0; b < BB; b++) acc[b] = 0.f;
    for (int k = lane; k < DD; k += 32) {
        float wv = __ldg(&wr[k]);
#pragma unroll
        for (int b = 0; b < BB; b++)
            acc[b] = fmaf(wv, __ldg(&in[b * DD + k]), acc[b]);
    }
#pragma unroll
    for (int b = 0; b < BB; b++) {
#pragma unroll
        for (int off = 16; off > 0; off >>= 1)
            acc[b] += __shfl_xor_sync(0xFFFFFFFFu, acc[b], off);
    }
    if (lane == 0) {
        float bb = bias[j];
#pragma unroll
        for (int b = 0; b < BB; b++) {
            float v = acc[b] + bb;
            if (layer == 0) v = fmaxf(v, 0.f);
            out[b * DD + j] = v;
        }
    }
}

// ---------------- segment metadata ------------------------------------------
__global__ void meta_kernel(const int* __restrict__ bboxes,
                            float* __restrict__ att_mask_out) {
    __shared__ int counts[BB];
    __shared__ int offs[BB];
    int t = threadIdx.x;
    if (t < BB) counts[t] = 0;
    __syncthreads();
    int im = bboxes[t * 5];
    atomicAdd(&counts[im], 1);
    __syncthreads();
    if (t == 0) {
        int s = 0;
        for (int b = 0; b < BB; b++) { offs[b] = s; s += counts[b]; }
    }
    __syncthreads();
    g_pos[t] = t - offs[im];
    for (int i = t; i < BB * MAXB; i += NBOX) {
        int b = i / MAXB, m = i % MAXB;
        att_mask_out[i] = (m < counts[b]) ? 1.0f : 0.0f;
    }
}

// ---------------- GEMM 1: fm1 = relu(features[:,1:] @ m1w^T + m1b) ----------
// M=1024, N=768, K=256. 64x64 tiles, 3xTF32 mma.
__global__ __launch_bounds__(128) void gemm_fm1_kernel(const float* __restrict__ feat,
                                                       const float* __restrict__ w,
                                                       const float* __restrict__ bias) {
    __shared__ unsigned Ah[32][68], Al[32][68], Bh[32][68], Bl[32][68];
    int bm = blockIdx.x, bn = blockIdx.y, tid = threadIdx.x;
    int wid = tid >> 5, lane = tid & 31, gid = lane >> 2, tig = lane & 3;
    int wm = wid >> 1, wn = wid & 1;
    float c[2][4][4];
#pragma unroll
    for (int mt = 0; mt < 2; mt++)
#pragma unroll
        for (int nt = 0; nt < 4; nt++)
#pragma unroll
            for (int q = 0; q < 4; q++) c[mt][nt][q] = 0.f;

    for (int kt = 0; kt < DDETR; kt += 32) {
        // A: features rows (stride 257, col offset 1) — scalar loads
        int kk = tid & 31, r0 = tid >> 5;
#pragma unroll
        for (int i = 0; i < 16; i++) {
            int r = r0 + i * 4;
            float v = feat[(size_t)(bm * 64 + r) * (DDETR + 1) + 1 + kt + kk];
            split_tf32(v, Ah[kk][r], Al[kk][r]);
        }
        load_tile_f4(w, DDETR, bn * 64, kt, Bh, Bl, tid);
        __syncthreads();
        mma_ktile(Ah, Al, Bh, Bl, wm, wn, gid, tig, c);
        __syncthreads();
    }
    int row0 = bm * 64 + wm * 32, col0 = bn * 64 + wn * 32;
#pragma unroll
    for (int nt = 0; nt < 4; nt++) {
        int col = col0 + nt * 8 + tig * 2;
        float bv0 = bias[col], bv1 = bias[col + 1];
#pragma unroll
        for (int mt = 0; mt < 2; mt++) {
            int r = row0 + mt * 16 + gid;
            float* d0 = &g_fm1[(size_t)r * DD + col];
            d0[0] = fmaxf(c[mt][nt][0] + bv0, 0.f);
            d0[1] = fmaxf(c[mt][nt][1] + bv1, 0.f);
            float* d1 = &g_fm1[(size_t)(r + 8) * DD + col];
            d1[0] = fmaxf(c[mt][nt][2] + bv0, 0.f);
            d1[1] = fmaxf(c[mt][nt][3] + bv1, 0.f);
        }
    }
}

// ---------------- GEMM 2: fm = fm1 @ m2w^T + m2b -----------------------------
__global__ __launch_bounds__(128) void gemm_fm2_kernel(const float* __restrict__ w,
                                                       const float* __restrict__ bias) {
    __shared__ unsigned Ah[32][68], Al[32][68], Bh[32][68], Bl[32][68];
    int bm = blockIdx.x, bn = blockIdx.y, tid = threadIdx.x;
    int wid = tid >> 5, lane = tid & 31, gid = lane >> 2, tig = lane & 3;
    int wm = wid >> 1, wn = wid & 1;
    float c[2][4][4];
#pragma unroll
    for (int mt = 0; mt < 2; mt++)
#pragma unroll
        for (int nt = 0; nt < 4; nt++)
#pragma unroll
            for (int q = 0; q < 4; q++) c[mt][nt][q] = 0.f;

    for (int kt = 0; kt < DD; kt += 32) {
        load_tile_f4(g_fm1, DD, bm * 64, kt, Ah, Al, tid);
        load_tile_f4(w, DD, bn * 64, kt, Bh, Bl, tid);
        __syncthreads();
        mma_ktile(Ah, Al, Bh, Bl, wm, wn, gid, tig, c);
        __syncthreads();
    }
    int row0 = bm * 64 + wm * 32, col0 = bn * 64 + wn * 32;
#pragma unroll
    for (int nt = 0; nt < 4; nt++) {
        int col = col0 + nt * 8 + tig * 2;
        float bv0 = bias[col], bv1 = bias[col + 1];
#pragma unroll
        for (int mt = 0; mt < 2; mt++) {
            int r = row0 + mt * 16 + gid;
            float* d0 = &g_fm[(size_t)r * DD + col];
            d0[0] = c[mt][nt][0] + bv0;
            d0[1] = c[mt][nt][1] + bv1;
            float* d1 = &g_fm[(size_t)(r + 8) * DD + col];
            d1[0] = c[mt][nt][2] + bv0;
            d1[1] = c[mt][nt][3] + bv1;
        }
    }
}

// ---------------- GEMM 3 + scatter: h -> vis_output --------------------------
// h[n] = [xt[img[n]] | fm[n]] @ pw^T + pb, K=1536
__global__ __launch_bounds__(128) void gemm_h_kernel(const int* __restrict__ bboxes,
                                                     const float* __restrict__ pw,
                                                     const float* __restrict__ pb,
                                                     float* __restrict__ out_vis) {
    __shared__ unsigned Ah[32][68], Al[32][68], Bh[32][68], Bl[32][68];
    __shared__ int simg[64];
    int bm = blockIdx.x, bn = blockIdx.y, tid = threadIdx.x;
    int wid = tid >> 5, lane = tid & 31, gid = lane >> 2, tig = lane & 3;
    int wm = wid >> 1, wn = wid & 1;
    if (tid < 64) simg[tid] = bboxes[(bm * 64 + tid) * 5];
    __syncthreads();

    float c[2][4][4];
#pragma unroll
    for (int mt = 0; mt < 2; mt++)
#pragma unroll
        for (int nt = 0; nt < 4; nt++)
#pragma unroll
            for (int q = 0; q < 4; q++) c[mt][nt][q] = 0.f;

    for (int kt = 0; kt < 2 * DD; kt += 32) {
        // A: gathered xt for k<768, fm for k>=768
#pragma unroll
        for (int i = 0; i < 4; i++) {
            int f = tid + i * 128;
            int r = f >> 3, c4 = (f & 7) * 4;
            int kg = kt + c4;
            const float* src = (kg < DD)
                ? (g_xt + (size_t)simg[r] * DD + kg)
                : (g_fm + (size_t)(bm * 64 + r) * DD + (kg - DD));
            float4 v = *reinterpret_cast<const float4*>(src);
            split_tf32(v.x, Ah[c4 + 0][r], Al[c4 + 0][r]);
            split_tf32(v.y, Ah[c4 + 1][r], Al[c4 + 1][r]);
            split_tf32(v.z, Ah[c4 + 2][r], Al[c4 + 2][r]);
            split_tf32(v.w, Ah[c4 + 3][r], Al[c4 + 3][r]);
        }
        load_tile_f4(pw, 2 * DD, bn * 64, kt, Bh, Bl, tid);
        __syncthreads();
        mma_ktile(Ah, Al, Bh, Bl, wm, wn, gid, tig, c);
        __syncthreads();
    }
    int col0 = bn * 64 + wn * 32;
#pragma unroll
    for (int mt = 0; mt < 2; mt++) {
        int rl0 = wm * 32 + mt * 16 + gid;       // local row for c0/c1
        int rl1 = rl0 + 8;                        // local row for c2/c3
        int n0 = bm * 64 + rl0, n1 = bm * 64 + rl1;
        int p0 = g_pos[n0], p1 = g_pos[n1];
        int im0 = simg[rl0], im1 = simg[rl1];
#pragma unroll
        for (int nt = 0; nt < 4; nt++) {
            int col = col0 + nt * 8 + tig * 2;
            float bv0 = pb[col], bv1 = pb[col + 1];
            if (p0 < MAXB) {
                float* d = out_vis + ((size_t)im0 * MAXB + p0) * DD + col;
                d[0] = c[mt][nt][0] + bv0;
                d[1] = c[mt][nt][1] + bv1;
            }
            if (p1 < MAXB) {
                float* d = out_vis + ((size_t)im1 * MAXB + p1) * DD + col;
                d[0] = c[mt][nt][2] + bv0;
                d[1] = c[mt][nt][3] + bv1;
            }
        }
    }
}

// ---------------- launch -----------------------------------------------------
extern "C" void kernel_launch(void* const* d_in, const int* in_sizes, int n_in,
                              void* d_out, int out_size) {
    (void)in_sizes; (void)n_in; (void)out_size;
    const float* inputs   = (const float*)d_in[0];
    const int*   bboxes   = (const int*)  d_in[1];
    const float* features = (const float*)d_in[2];
    const float* t1w = (const float*)d_in[3],  *t1b = (const float*)d_in[4];
    const float* t2w = (const float*)d_in[5],  *t2b = (const float*)d_in[6];
    const float* d1w = (const float*)d_in[7],  *d1b = (const float*)d_in[8];
    const float* d2w = (const float*)d_in[9],  *d2b = (const float*)d_in[10];
    const float* m1w = (const float*)d_in[11], *m1b = (const float*)d_in[12];
    const float* m2w = (const float*)d_in[13], *m2b = (const float*)d_in[14];
    const float* pw  = (const float*)d_in[15], *pb  = (const float*)d_in[16];

    float* out      = (float*)d_out;
    float* out_vis  = out;
    float* out_mask = out + VIS_ELEMS;
    float* out_retx = out + VIS_ELEMS + MASK_ELEMS;

    zero_vis_kernel<<<512, 256>>>((float4*)out_vis);
    mean_partial_kernel<<<BB * NC, 192>>>(inputs);
    mean_final_kernel<<<12, 256>>>();
    small_mlp_kernel<<<192, 256>>>(0, t1w, t1b, d1w, d1b, nullptr);
    small_mlp_kernel<<<192, 256>>>(1, t2w, t2b, d2w, d2b, out_retx);
    meta_kernel<<<1, NBOX>>>(bboxes, out_mask);
    gemm_fm1_kernel<<<dim3(16, 12), 128>>>(features, m1w, m1b);
    gemm_fm2_kernel<<<dim3(16, 12), 128>>>(m2w, m2b);
    gemm_h_kernel<<<dim3(16, 12), 128>>>(bboxes, pw, pb, out_vis);
}

// round 4
// speedup vs baseline: 1.0368x; 1.0368x over previous
#include <cuda_runtime.h>
#include <cstdint>

// Problem constants
#define BB 16
#define TT 4096
#define DD 768
#define NBOX 1024
#define MAXB 128
#define DDETR 256
#define VIS_ELEMS (BB*MAXB*DD)
#define MASK_ELEMS (BB*MAXB)
#define NC 64

// ---------------- scratch (device globals) -----------------------------------
__device__ __align__(16) float g_partial[BB*NC*DD];
__device__ __align__(16) float g_x[BB*DD];
__device__ __align__(16) float g_h1t[BB*DD];
__device__ __align__(16) float g_h1d[BB*DD];
__device__ __align__(16) float g_xt[BB*DD];
__device__ __align__(16) float g_hb[BB*DD];          // folded bias for gemm_h
__device__ int g_pos[NBOX];

// tf32-prerounded hi/lo operand arrays (stored as float)
__device__ __align__(16) float g_w1h[768*256],  g_w1l[768*256];
__device__ __align__(16) float g_w2h[768*768],  g_w2l[768*768];
__device__ __align__(16) float g_wph[768*768],  g_wpl[768*768];   // pw[:,768:1536]
__device__ __align__(16) float g_feath[1024*256], g_featl[1024*256];
__device__ __align__(16) float g_fm1h[1024*768],  g_fm1l[1024*768];
__device__ __align__(16) float g_fmh[1024*768],   g_fml[1024*768];

// ---------------- tf32 helpers ------------------------------------------------
__device__ __forceinline__ float tf32r(float x) {
    unsigned r;
    asm("cvt.rna.tf32.f32 %0, %1;" : "=r"(r) : "f"(x));
    return __uint_as_float(r);
}
__device__ __forceinline__ void mma_tf32(float* c, const uint32_t a[4],
                                         uint32_t b0, uint32_t b1) {
    asm("mma.sync.aligned.m16n8k8.row.col.f32.tf32.tf32.f32 "
        "{%0,%1,%2,%3}, {%4,%5,%6,%7}, {%8,%9}, {%0,%1,%2,%3};"
        : "+f"(c[0]), "+f"(c[1]), "+f"(c[2]), "+f"(c[3])
        : "r"(a[0]), "r"(a[1]), "r"(a[2]), "r"(a[3]), "r"(b0), "r"(b1));
}

// one 32-k chunk of MMAs on a 64x64 tile, 4 warps (wm,wn in {0,1}), 32x32/warp
__device__ __forceinline__ void mma_chunk(const uint32_t A[32][68],
                                          const uint32_t B[32][68],
                                          int wm, int wn, int gid, int tig,
                                          float c[2][4][4]) {
#pragma unroll
    for (int ks = 0; ks < 4; ks++) {
        const int k0 = ks * 8;
        uint32_t a[2][4];
#pragma unroll
        for (int mt = 0; mt < 2; mt++) {
            int r = wm * 32 + mt * 16 + gid;
            a[mt][0] = A[k0 + tig][r];     a[mt][1] = A[k0 + tig][r + 8];
            a[mt][2] = A[k0 + tig + 4][r]; a[mt][3] = A[k0 + tig + 4][r + 8];
        }
#pragma unroll
        for (int nt = 0; nt < 4; nt++) {
            int cn = wn * 32 + nt * 8 + gid;
            uint32_t b0 = B[k0 + tig][cn], b1 = B[k0 + tig + 4][cn];
#pragma unroll
            for (int mt = 0; mt < 2; mt++)
                mma_tf32(c[mt][nt], a[mt], b0, b1);
        }
    }
}

// ---------------- zero vis_output ----------------------------------------------
__global__ void zero_vis_kernel(float4* __restrict__ out) {
    const int n4 = VIS_ELEMS / 4;
    for (int i = blockIdx.x * blockDim.x + threadIdx.x; i < n4;
         i += gridDim.x * blockDim.x)
        out[i] = make_float4(0.f, 0.f, 0.f, 0.f);
}

// ---------------- mean pass 1 ---------------------------------------------------
__global__ void mean_partial_kernel(const float* __restrict__ in) {
    int b = blockIdx.x >> 6;
    int c = blockIdx.x & 63;
    const float4* p = reinterpret_cast<const float4*>(
        in + ((size_t)b * TT + (size_t)c * 64) * DD) + threadIdx.x;
    float4 acc = make_float4(0.f, 0.f, 0.f, 0.f);
    #pragma unroll 8
    for (int r = 0; r < 64; r++) {
        float4 v = p[(size_t)r * (DD / 4)];
        acc.x += v.x; acc.y += v.y; acc.z += v.z; acc.w += v.w;
    }
    reinterpret_cast<float4*>(g_partial + ((size_t)b * NC + c) * DD)[threadIdx.x] = acc;
}

// ---------------- mean pass 2 ---------------------------------------------------
__global__ void mean_final_kernel() {
    int i = blockIdx.x * blockDim.x + threadIdx.x;
    int b  = i / (DD / 4);
    int c4 = i % (DD / 4);
    const float4* p = reinterpret_cast<const float4*>(g_partial)
                      + (size_t)b * NC * (DD / 4) + c4;
    float4 acc = make_float4(0.f, 0.f, 0.f, 0.f);
    #pragma unroll 8
    for (int c = 0; c < NC; c++) {
        float4 v = p[(size_t)c * (DD / 4)];
        acc.x += v.x; acc.y += v.y; acc.z += v.z; acc.w += v.w;
    }
    const float s = 1.0f / (float)TT;
    acc.x *= s; acc.y *= s; acc.z *= s; acc.w *= s;
    reinterpret_cast<float4*>(g_x)[(size_t)b * (DD / 4) + c4] = acc;
}

// ---------------- small MLP: smem-staged x, 4 cols/warp -------------------------
// grid = 48 (24 per branch), block = 256
__global__ __launch_bounds__(256) void mlp_kernel(int layer,
        const float* __restrict__ wt, const float* __restrict__ bt,
        const float* __restrict__ wd, const float* __restrict__ bd,
        float* __restrict__ retx_out) {
    __shared__ __align__(16) float xs[BB * DD];
    int branch = blockIdx.x / 24;
    const float* in   = (layer == 0) ? g_x : (branch ? g_h1d : g_h1t);
    const float* w    = branch ? wd : wt;
    const float* bias = branch ? bd : bt;
    float* out        = (layer == 0) ? (branch ? g_h1d : g_h1t)
                                     : (branch ? retx_out : g_xt);
    {
        const float4* s = reinterpret_cast<const float4*>(in);
        float4* d = reinterpret_cast<float4*>(xs);
        for (int i = threadIdx.x; i < BB * DD / 4; i += 256) d[i] = s[i];
    }
    __syncthreads();

    int warp = threadIdx.x >> 5, lane = threadIdx.x & 31;
    int j0 = (blockIdx.x % 24) * 32 + warp * 4;
    float acc[4][BB];
#pragma unroll
    for (int j = 0; j < 4; j++)
#pragma unroll
        for (int b = 0; b < BB; b++) acc[j][b] = 0.f;

    for (int it = 0; it < DD / 128; it++) {
        int k = it * 128 + lane * 4;
        float4 wv[4];
#pragma unroll
        for (int j = 0; j < 4; j++)
            wv[j] = *reinterpret_cast<const float4*>(&w[(size_t)(j0 + j) * DD + k]);
#pragma unroll
        for (int b = 0; b < BB; b++) {
            float4 xv = *reinterpret_cast<const float4*>(&xs[b * DD + k]);
#pragma unroll
            for (int j = 0; j < 4; j++) {
                acc[j][b] = fmaf(wv[j].x, xv.x, acc[j][b]);
                acc[j][b] = fmaf(wv[j].y, xv.y, acc[j][b]);
                acc[j][b] = fmaf(wv[j].z, xv.z, acc[j][b]);
                acc[j][b] = fmaf(wv[j].w, xv.w, acc[j][b]);
            }
        }
    }
#pragma unroll
    for (int j = 0; j < 4; j++)
#pragma unroll
        for (int b = 0; b < BB; b++)
#pragma unroll
            for (int off = 16; off > 0; off >>= 1)
                acc[j][b] += __shfl_xor_sync(0xFFFFFFFFu, acc[j][b], off);
    if (lane == 0) {
#pragma unroll
        for (int j = 0; j < 4; j++) {
            float bb = bias[j0 + j];
#pragma unroll
            for (int b = 0; b < BB; b++) {
                float v = acc[j][b] + bb;
                if (layer == 0) v = fmaxf(v, 0.f);
                out[b * DD + j0 + j] = v;
            }
        }
    }
}

// ---------------- hb = pb + xt @ pw[:, :768]^T (folded gemm_h bias) ------------
// grid = 24, block = 256
__global__ __launch_bounds__(256) void hb_kernel(const float* __restrict__ pw,
                                                 const float* __restrict__ pb) {
    __shared__ __align__(16) float xs[BB * DD];
    {
        const float4* s = reinterpret_cast<const float4*>(g_xt);
        float4* d = reinterpret_cast<float4*>(xs);
        for (int i = threadIdx.x; i < BB * DD / 4; i += 256) d[i] = s[i];
    }
    __syncthreads();
    int warp = threadIdx.x >> 5, lane = threadIdx.x & 31;
    int j0 = blockIdx.x * 32 + warp * 4;
    float acc[4][BB];
#pragma unroll
    for (int j = 0; j < 4; j++)
#pragma unroll
        for (int b = 0; b < BB; b++) acc[j][b] = 0.f;
    for (int it = 0; it < DD / 128; it++) {
        int k = it * 128 + lane * 4;
        float4 wv[4];
#pragma unroll
        for (int j = 0; j < 4; j++)
            wv[j] = *reinterpret_cast<const float4*>(&pw[(size_t)(j0 + j) * (2 * DD) + k]);
#pragma unroll
        for (int b = 0; b < BB; b++) {
            float4 xv = *reinterpret_cast<const float4*>(&xs[b * DD + k]);
#pragma unroll
            for (int j = 0; j < 4; j++) {
                acc[j][b] = fmaf(wv[j].x, xv.x, acc[j][b]);
                acc[j][b] = fmaf(wv[j].y, xv.y, acc[j][b]);
                acc[j][b] = fmaf(wv[j].z, xv.z, acc[j][b]);
                acc[j][b] = fmaf(wv[j].w, xv.w, acc[j][b]);
            }
        }
    }
#pragma unroll
    for (int j = 0; j < 4; j++)
#pragma unroll
        for (int b = 0; b < BB; b++)
#pragma unroll
            for (int off = 16; off > 0; off >>= 1)
                acc[j][b] += __shfl_xor_sync(0xFFFFFFFFu, acc[j][b], off);
    if (lane == 0) {
#pragma unroll
        for (int j = 0; j < 4; j++) {
            float bb = pb[j0 + j];
#pragma unroll
            for (int b = 0; b < BB; b++)
                g_hb[b * DD + j0 + j] = acc[j][b] + bb;
        }
    }
}

// ---------------- segment metadata ----------------------------------------------
__global__ void meta_kernel(const int* __restrict__ bboxes,
                            float* __restrict__ att_mask_out) {
    __shared__ int counts[BB];
    __shared__ int offs[BB];
    int t = threadIdx.x;
    if (t < BB) counts[t] = 0;
    __syncthreads();
    int im = bboxes[t * 5];
    atomicAdd(&counts[im], 1);
    __syncthreads();
    if (t == 0) {
        int s = 0;
        for (int b = 0; b < BB; b++) { offs[b] = s; s += counts[b]; }
    }
    __syncthreads();
    g_pos[t] = t - offs[im];
    for (int i = t; i < BB * MAXB; i += NBOX) {
        int b = i / MAXB, m = i % MAXB;
        att_mask_out[i] = (m < counts[b]) ? 1.0f : 0.0f;
    }
}

// ---------------- pre-convert operands to tf32 hi/lo ----------------------------
#define CN1 (768*256)
#define CN2 (768*768)
#define CN3 (768*768)
#define CN4 (1024*256)
__global__ void conv_kernel(const float* __restrict__ m1w, const float* __restrict__ m2w,
                            const float* __restrict__ pw,  const float* __restrict__ feat) {
    const int TOT = CN1 + CN2 + CN3 + CN4;
    for (int i = blockIdx.x * blockDim.x + threadIdx.x; i < TOT;
         i += gridDim.x * blockDim.x) {
        float v; float *oh, *ol; int o;
        if (i < CN1) { o = i; v = m1w[o]; oh = g_w1h; ol = g_w1l; }
        else if (i < CN1 + CN2) { o = i - CN1; v = m2w[o]; oh = g_w2h; ol = g_w2l; }
        else if (i < CN1 + CN2 + CN3) {
            o = i - CN1 - CN2;
            int col = o / 768, k = o - col * 768;
            v = pw[(size_t)col * (2 * DD) + DD + k];
            oh = g_wph; ol = g_wpl;
        } else {
            o = i - CN1 - CN2 - CN3;
            int n = o >> 8, k = o & 255;
            v = feat[(size_t)n * (DDETR + 1) + 1 + k];
            oh = g_feath; ol = g_featl;
        }
        float h = tf32r(v);
        oh[o] = h; ol[o] = tf32r(v - h);
    }
}

// ---------------- 3xTF32 GEMM, 64x64 tiles, reg-prefetch double buffer ----------
// mode 0: fm1 = relu(feat @ m1w^T + m1b)        K=256, out hi/lo
// mode 1: fm  = fm1 @ m2w^T + m2b               K=768, out hi/lo
// mode 2: h   = fm @ pw2^T + hb[img]  -> scatter K=768
__global__ __launch_bounds__(128) void tf32_gemm(int mode,
        const float* __restrict__ bias,
        const int* __restrict__ bboxes,
        float* __restrict__ out_vis) {
    __shared__ uint32_t Sa[2][32][68];
    __shared__ uint32_t Sb[2][32][68];
    __shared__ int simg[64];

    const int tid = threadIdx.x;
    const int bm = blockIdx.x, bn = blockIdx.y;
    const int wid = tid >> 5, lane = tid & 31, gid = lane >> 2, tig = lane & 3;
    const int wm = wid >> 1, wn = wid & 1;
    const int K = (mode == 0) ? 256 : 768;
    const int npt = K / 32, nch = 3 * npt;

    const float *Ahi, *Alo, *Bhi, *Blo;
    if (mode == 0)      { Ahi = g_feath; Alo = g_featl; Bhi = g_w1h; Blo = g_w1l; }
    else if (mode == 1) { Ahi = g_fm1h;  Alo = g_fm1l;  Bhi = g_w2h; Blo = g_w2l; }
    else                { Ahi = g_fmh;   Alo = g_fml;   Bhi = g_wph; Blo = g_wpl; }

    if (mode == 2 && tid < 64) simg[tid] = bboxes[(bm * 64 + tid) * 5];

    float acc[2][4][4];
#pragma unroll
    for (int mt = 0; mt < 2; mt++)
#pragma unroll
        for (int nt = 0; nt < 4; nt++)
#pragma unroll
            for (int q = 0; q < 4; q++) acc[mt][nt][q] = 0.f;

    float4 pa[4], pbv[4];
    // prefetch chunk 0
    {
        const float* Asrc = Ahi + (size_t)(bm * 64) * K;
        const float* Bsrc = Bhi + (size_t)(bn * 64) * K;
#pragma unroll
        for (int i = 0; i < 4; i++) {
            int f = tid + i * 128, r = f >> 3, c4 = (f & 7) * 4;
            pa[i]  = *reinterpret_cast<const float4*>(Asrc + (size_t)r * K + c4);
            pbv[i] = *reinterpret_cast<const float4*>(Bsrc + (size_t)r * K + c4);
        }
    }

    for (int c = 0; c < nch; c++) {
        int buf = c & 1;
#pragma unroll
        for (int i = 0; i < 4; i++) {
            int f = tid + i * 128, r = f >> 3, c4 = (f & 7) * 4;
            Sa[buf][c4 + 0][r] = __float_as_uint(pa[i].x);
            Sa[buf][c4 + 1][r] = __float_as_uint(pa[i].y);
            Sa[buf][c4 + 2][r] = __float_as_uint(pa[i].z);
            Sa[buf][c4 + 3][r] = __float_as_uint(pa[i].w);
            Sb[buf][c4 + 0][r] = __float_as_uint(pbv[i].x);
            Sb[buf][c4 + 1][r] = __float_as_uint(pbv[i].y);
            Sb[buf][c4 + 2][r] = __float_as_uint(pbv[i].z);
            Sb[buf][c4 + 3][r] = __float_as_uint(pbv[i].w);
        }
        __syncthreads();
        if (c + 1 < nch) {
            int cn = c + 1;
            int term = cn / npt, kc = (cn - term * npt) * 32;
            const float* Asrc = ((term == 1) ? Alo : Ahi) + (size_t)(bm * 64) * K + kc;
            const float* Bsrc = ((term == 2) ? Blo : Bhi) + (size_t)(bn * 64) * K + kc;
#pragma unroll
            for (int i = 0; i < 4; i++) {
                int f = tid + i * 128, r = f >> 3, c4 = (f & 7) * 4;
                pa[i]  = *reinterpret_cast<const float4*>(Asrc + (size_t)r * K + c4);
                pbv[i] = *reinterpret_cast<const float4*>(Bsrc + (size_t)r * K + c4);
            }
        }
        mma_chunk(Sa[buf], Sb[buf], wm, wn, gid, tig, acc);
    }

    int row0 = bm * 64 + wm * 32, col0 = bn * 64 + wn * 32;
    if (mode == 2) {
#pragma unroll
        for (int mt = 0; mt < 2; mt++) {
            int rl0 = wm * 32 + mt * 16 + gid, rl1 = rl0 + 8;
            int n0 = bm * 64 + rl0, n1 = bm * 64 + rl1;
            int p0 = g_pos[n0], p1 = g_pos[n1];
            int im0 = simg[rl0], im1 = simg[rl1];
#pragma unroll
            for (int nt = 0; nt < 4; nt++) {
                int col = col0 + nt * 8 + tig * 2;
                if (p0 < MAXB) {
                    float* d = out_vis + ((size_t)im0 * MAXB + p0) * DD + col;
                    d[0] = acc[mt][nt][0] + g_hb[im0 * DD + col];
                    d[1] = acc[mt][nt][1] + g_hb[im0 * DD + col + 1];
                }
                if (p1 < MAXB) {
                    float* d = out_vis + ((size_t)im1 * MAXB + p1) * DD + col;
                    d[0] = acc[mt][nt][2] + g_hb[im1 * DD + col];
                    d[1] = acc[mt][nt][3] + g_hb[im1 * DD + col + 1];
                }
            }
        }
    } else {
        float* oh = (mode == 0) ? g_fm1h : g_fmh;
        float* ol = (mode == 0) ? g_fm1l : g_fml;
#pragma unroll
        for (int nt = 0; nt < 4; nt++) {
            int col = col0 + nt * 8 + tig * 2;
            float bv0 = bias[col], bv1 = bias[col + 1];
#pragma unroll
            for (int mt = 0; mt < 2; mt++) {
                int r = row0 + mt * 16 + gid;
                float v00 = acc[mt][nt][0] + bv0, v01 = acc[mt][nt][1] + bv1;
                float v10 = acc[mt][nt][2] + bv0, v11 = acc[mt][nt][3] + bv1;
                if (mode == 0) {
                    v00 = fmaxf(v00, 0.f); v01 = fmaxf(v01, 0.f);
                    v10 = fmaxf(v10, 0.f); v11 = fmaxf(v11, 0.f);
                }
                size_t o0 = (size_t)r * DD + col, o1 = (size_t)(r + 8) * DD + col;
                float h;
                h = tf32r(v00); oh[o0]     = h; ol[o0]     = tf32r(v00 - h);
                h = tf32r(v01); oh[o0 + 1] = h; ol[o0 + 1] = tf32r(v01 - h);
                h = tf32r(v10); oh[o1]     = h; ol[o1]     = tf32r(v10 - h);
                h = tf32r(v11); oh[o1 + 1] = h; ol[o1 + 1] = tf32r(v11 - h);
            }
        }
    }
}

// ---------------- launch ----------------------------------------------------------
extern "C" void kernel_launch(void* const* d_in, const int* in_sizes, int n_in,
                              void* d_out, int out_size) {
    (void)in_sizes; (void)n_in; (void)out_size;
    const float* inputs   = (const float*)d_in[0];
    const int*   bboxes   = (const int*)  d_in[1];
    const float* features = (const float*)d_in[2];
    const float* t1w = (const float*)d_in[3],  *t1b = (const float*)d_in[4];
    const float* t2w = (const float*)d_in[5],  *t2b = (const float*)d_in[6];
    const float* d1w = (const float*)d_in[7],  *d1b = (const float*)d_in[8];
    const float* d2w = (const float*)d_in[9],  *d2b = (const float*)d_in[10];
    const float* m1w = (const float*)d_in[11], *m1b = (const float*)d_in[12];
    const float* m2w = (const float*)d_in[13], *m2b = (const float*)d_in[14];
    const float* pw  = (const float*)d_in[15], *pb  = (const float*)d_in[16];

    float* out      = (float*)d_out;
    float* out_vis  = out;
    float* out_mask = out + VIS_ELEMS;
    float* out_retx = out + VIS_ELEMS + MASK_ELEMS;

    conv_kernel<<<640, 256>>>(m1w, m2w, pw, features);           // 1
    mean_partial_kernel<<<BB * NC, 192>>>(inputs);               // 2
    mean_final_kernel<<<12, 256>>>();                            // 3
    zero_vis_kernel<<<512, 256>>>((float4*)out_vis);             // 4
    meta_kernel<<<1, NBOX>>>(bboxes, out_mask);                  // 5
    tf32_gemm<<<dim3(16, 12), 128>>>(0, m1b, bboxes, nullptr);   // 6  <- profiled
    mlp_kernel<<<48, 256>>>(0, t1w, t1b, d1w, d1b, nullptr);     // 7
    mlp_kernel<<<48, 256>>>(1, t2w, t2b, d2w, d2b, out_retx);    // 8
    hb_kernel<<<24, 256>>>(pw, pb);                              // 9
    tf32_gemm<<<dim3(16, 12), 128>>>(1, m2b, bboxes, nullptr);   // 10
    tf32_gemm<<<dim3(16, 12), 128>>>(2, nullptr, bboxes, out_vis); // 11
}

// round 5
// speedup vs baseline: 2.1273x; 2.0517x over previous
#include <cuda_runtime.h>
#include <cuda_fp16.h>
#include <cstdint>

// Problem constants
#define BB 16
#define TT 4096
#define DD 768
#define NBOX 1024
#define MAXB 128
#define DDETR 256
#define VIS_ELEMS (BB*MAXB*DD)
#define MASK_ELEMS (BB*MAXB)
#define NC 64

// ---------------- scratch (device globals) -----------------------------------
__device__ __align__(16) float g_partial[BB*NC*DD];
__device__ __align__(16) float g_x[BB*DD];
__device__ __align__(16) float g_h1t[BB*DD];
__device__ __align__(16) float g_h1d[BB*DD];
__device__ __align__(16) float g_xt[BB*DD];
__device__ __align__(16) float g_hb[BB*DD];          // folded bias for gemm_h
__device__ int g_pos[NBOX];

// fp16 hi/lo operand arrays (row-major, k contiguous)
__device__ __align__(16) __half g_w1h[768*256],  g_w1l[768*256];
__device__ __align__(16) __half g_w2h[768*768],  g_w2l[768*768];
__device__ __align__(16) __half g_wph[768*768],  g_wpl[768*768];   // pw[:,768:]
__device__ __align__(16) __half g_feath[1024*256], g_featl[1024*256];
__device__ __align__(16) __half g_fm1h[1024*768],  g_fm1l[1024*768];
__device__ __align__(16) __half g_fmh[1024*768],   g_fml[1024*768];

// ---------------- helpers -------------------------------------------------------
__device__ __forceinline__ uint32_t smem_u32(const void* p) {
    uint32_t r;
    asm("{ .reg .u64 t; cvta.to.shared.u64 t, %1; cvt.u32.u64 %0, t; }"
        : "=r"(r) : "l"(p));
    return r;
}
#define CP_ASYNC16(dst, src) \
    asm volatile("cp.async.cg.shared.global [%0], [%1], 16;" \
                 :: "r"(dst), "l"(src) : "memory")
#define CP_COMMIT() asm volatile("cp.async.commit_group;" ::: "memory")
#define CP_WAIT(n)  asm volatile("cp.async.wait_group %0;" :: "n"(n) : "memory")

__device__ __forceinline__ void h2split(float v, __half2* oh, __half2* ol,
                                        float v1) {
    __half h0 = __float2half_rn(v),  h1 = __float2half_rn(v1);
    __half l0 = __float2half_rn(v - __half2float(h0));
    __half l1 = __float2half_rn(v1 - __half2float(h1));
    *oh = __halves2half2(h0, h1);
    *ol = __halves2half2(l0, l1);
}

// ---------------- zero vis_output ----------------------------------------------
__global__ void zero_vis_kernel(float4* __restrict__ out) {
    const int n4 = VIS_ELEMS / 4;
    for (int i = blockIdx.x * blockDim.x + threadIdx.x; i < n4;
         i += gridDim.x * blockDim.x)
        out[i] = make_float4(0.f, 0.f, 0.f, 0.f);
}

// ---------------- mean pass 1 ----------------------------------------------------
__global__ void mean_partial_kernel(const float* __restrict__ in) {
    int b = blockIdx.x >> 6;
    int c = blockIdx.x & 63;
    const float4* p = reinterpret_cast<const float4*>(
        in + ((size_t)b * TT + (size_t)c * 64) * DD) + threadIdx.x;
    float4 acc = make_float4(0.f, 0.f, 0.f, 0.f);
    #pragma unroll 8
    for (int r = 0; r < 64; r++) {
        float4 v = p[(size_t)r * (DD / 4)];
        acc.x += v.x; acc.y += v.y; acc.z += v.z; acc.w += v.w;
    }
    reinterpret_cast<float4*>(g_partial + ((size_t)b * NC + c) * DD)[threadIdx.x] = acc;
}

// ---------------- mean pass 2 ----------------------------------------------------
__global__ void mean_final_kernel() {
    int i = blockIdx.x * blockDim.x + threadIdx.x;
    int b  = i / (DD / 4);
    int c4 = i % (DD / 4);
    const float4* p = reinterpret_cast<const float4*>(g_partial)
                      + (size_t)b * NC * (DD / 4) + c4;
    float4 acc = make_float4(0.f, 0.f, 0.f, 0.f);
    #pragma unroll 8
    for (int c = 0; c < NC; c++) {
        float4 v = p[(size_t)c * (DD / 4)];
        acc.x += v.x; acc.y += v.y; acc.z += v.z; acc.w += v.w;
    }
    const float s = 1.0f / (float)TT;
    acc.x *= s; acc.y *= s; acc.z *= s; acc.w *= s;
    reinterpret_cast<float4*>(g_x)[(size_t)b * (DD / 4) + c4] = acc;
}

// ---------------- small MLP: smem-staged x, 4 cols/warp ---------------------------
__global__ __launch_bounds__(256) void mlp_kernel(int layer,
        const float* __restrict__ wt, const float* __restrict__ bt,
        const float* __restrict__ wd, const float* __restrict__ bd,
        float* __restrict__ retx_out) {
    __shared__ __align__(16) float xs[BB * DD];
    int branch = blockIdx.x / 24;
    const float* in   = (layer == 0) ? g_x : (branch ? g_h1d : g_h1t);
    const float* w    = branch ? wd : wt;
    const float* bias = branch ? bd : bt;
    float* out        = (layer == 0) ? (branch ? g_h1d : g_h1t)
                                     : (branch ? retx_out : g_xt);
    {
        const float4* s = reinterpret_cast<const float4*>(in);
        float4* d = reinterpret_cast<float4*>(xs);
        for (int i = threadIdx.x; i < BB * DD / 4; i += 256) d[i] = s[i];
    }
    __syncthreads();

    int warp = threadIdx.x >> 5, lane = threadIdx.x & 31;
    int j0 = (blockIdx.x % 24) * 32 + warp * 4;
    float acc[4][BB];
#pragma unroll
    for (int j = 0; j < 4; j++)
#pragma unroll
        for (int b = 0; b < BB; b++) acc[j][b] = 0.f;

    for (int it = 0; it < DD / 128; it++) {
        int k = it * 128 + lane * 4;
        float4 wv[4];
#pragma unroll
        for (int j = 0; j < 4; j++)
            wv[j] = *reinterpret_cast<const float4*>(&w[(size_t)(j0 + j) * DD + k]);
#pragma unroll
        for (int b = 0; b < BB; b++) {
            float4 xv = *reinterpret_cast<const float4*>(&xs[b * DD + k]);
#pragma unroll
            for (int j = 0; j < 4; j++) {
                acc[j][b] = fmaf(wv[j].x, xv.x, acc[j][b]);
                acc[j][b] = fmaf(wv[j].y, xv.y, acc[j][b]);
                acc[j][b] = fmaf(wv[j].z, xv.z, acc[j][b]);
                acc[j][b] = fmaf(wv[j].w, xv.w, acc[j][b]);
            }
        }
    }
#pragma unroll
    for (int j = 0; j < 4; j++)
#pragma unroll
        for (int b = 0; b < BB; b++)
#pragma unroll
            for (int off = 16; off > 0; off >>= 1)
                acc[j][b] += __shfl_xor_sync(0xFFFFFFFFu, acc[j][b], off);
    if (lane == 0) {
#pragma unroll
        for (int j = 0; j < 4; j++) {
            float bb = bias[j0 + j];
#pragma unroll
            for (int b = 0; b < BB; b++) {
                float v = acc[j][b] + bb;
                if (layer == 0) v = fmaxf(v, 0.f);
                out[b * DD + j0 + j] = v;
            }
        }
    }
}

// ---------------- hb = pb + xt @ pw[:, :768]^T -----------------------------------
__global__ __launch_bounds__(256) void hb_kernel(const float* __restrict__ pw,
                                                 const float* __restrict__ pb) {
    __shared__ __align__(16) float xs[BB * DD];
    {
        const float4* s = reinterpret_cast<const float4*>(g_xt);
        float4* d = reinterpret_cast<float4*>(xs);
        for (int i = threadIdx.x; i < BB * DD / 4; i += 256) d[i] = s[i];
    }
    __syncthreads();
    int warp = threadIdx.x >> 5, lane = threadIdx.x & 31;
    int j0 = blockIdx.x * 32 + warp * 4;
    float acc[4][BB];
#pragma unroll
    for (int j = 0; j < 4; j++)
#pragma unroll
        for (int b = 0; b < BB; b++) acc[j][b] = 0.f;
    for (int it = 0; it < DD / 128; it++) {
        int k = it * 128 + lane * 4;
        float4 wv[4];
#pragma unroll
        for (int j = 0; j < 4; j++)
            wv[j] = *reinterpret_cast<const float4*>(&pw[(size_t)(j0 + j) * (2 * DD) + k]);
#pragma unroll
        for (int b = 0; b < BB; b++) {
            float4 xv = *reinterpret_cast<const float4*>(&xs[b * DD + k]);
#pragma unroll
            for (int j = 0; j < 4; j++) {
                acc[j][b] = fmaf(wv[j].x, xv.x, acc[j][b]);
                acc[j][b] = fmaf(wv[j].y, xv.y, acc[j][b]);
                acc[j][b] = fmaf(wv[j].z, xv.z, acc[j][b]);
                acc[j][b] = fmaf(wv[j].w, xv.w, acc[j][b]);
            }
        }
    }
#pragma unroll
    for (int j = 0; j < 4; j++)
#pragma unroll
        for (int b = 0; b < BB; b++)
#pragma unroll
            for (int off = 16; off > 0; off >>= 1)
                acc[j][b] += __shfl_xor_sync(0xFFFFFFFFu, acc[j][b], off);
    if (lane == 0) {
#pragma unroll
        for (int j = 0; j < 4; j++) {
            float bb = pb[j0 + j];
#pragma unroll
            for (int b = 0; b < BB; b++)
                g_hb[b * DD + j0 + j] = acc[j][b] + bb;
        }
    }
}

// ---------------- segment metadata ------------------------------------------------
__global__ void meta_kernel(const int* __restrict__ bboxes,
                            float* __restrict__ att_mask_out) {
    __shared__ int counts[BB];
    __shared__ int offs[BB];
    int t = threadIdx.x;
    if (t < BB) counts[t] = 0;
    __syncthreads();
    int im = bboxes[t * 5];
    atomicAdd(&counts[im], 1);
    __syncthreads();
    if (t == 0) {
        int s = 0;
        for (int b = 0; b < BB; b++) { offs[b] = s; s += counts[b]; }
    }
    __syncthreads();
    g_pos[t] = t - offs[im];
    for (int i = t; i < BB * MAXB; i += NBOX) {
        int b = i / MAXB, m = i % MAXB;
        att_mask_out[i] = (m < counts[b]) ? 1.0f : 0.0f;
    }
}

// ---------------- convert operands to fp16 hi/lo -----------------------------------
#define CN1 (768*256)
#define CN2 (768*768)
#define CN3 (768*768)
#define CN4 (1024*256)
__global__ void conv_kernel(const float* __restrict__ m1w, const float* __restrict__ m2w,
                            const float* __restrict__ pw,  const float* __restrict__ feat) {
    const int TOT = CN1 + CN2 + CN3 + CN4;
    for (int i = blockIdx.x * blockDim.x + threadIdx.x; i < TOT;
         i += gridDim.x * blockDim.x) {
        float v; __half *oh, *ol; int o;
        if (i < CN1) { o = i; v = m1w[o]; oh = g_w1h; ol = g_w1l; }
        else if (i < CN1 + CN2) { o = i - CN1; v = m2w[o]; oh = g_w2h; ol = g_w2l; }
        else if (i < CN1 + CN2 + CN3) {
            o = i - CN1 - CN2;
            int col = o / 768, k = o - col * 768;
            v = pw[(size_t)col * (2 * DD) + DD + k];
            oh = g_wph; ol = g_wpl;
        } else {
            o = i - CN1 - CN2 - CN3;
            int n = o >> 8, k = o & 255;
            v = feat[(size_t)n * (DDETR + 1) + 1 + k];
            oh = g_feath; ol = g_featl;
        }
        __half h = __float2half_rn(v);
        oh[o] = h;
        ol[o] = __float2half_rn(v - __half2float(h));
    }
}

// ---------------- fp16 split GEMM: fused 3-term, cp.async double buffer ------------
// 64x64 tiles, 128 threads (4 warps of 32x32), k-chunks of 32 (16 half2 pairs).
// mode 0: fm1 = relu(feat @ m1w^T + m1b)   K=256
// mode 1: fm  = fm1 @ m2w^T + m2b          K=768
// mode 2: h   = fm @ pw2^T + hb[img]       K=768 -> scatter to vis_output
__global__ __launch_bounds__(128) void hgemm(int mode,
        const float* __restrict__ bias,
        const int* __restrict__ bboxes,
        float* __restrict__ out_vis) {
    // [buf][arr: Ah,Al,Bh,Bl][row 64][k2 16 pad->20]
    __shared__ uint32_t S[2][4][64][20];
    __shared__ int simg[64];

    const int tid = threadIdx.x;
    const int bm = blockIdx.x, bn = blockIdx.y;
    const int wid = tid >> 5, lane = tid & 31, gid = lane >> 2, tig = lane & 3;
    const int wm = wid >> 1, wn = wid & 1;
    const int K = (mode == 0) ? 256 : 768;
    const int K2 = K >> 1;
    const int nch = K / 32;

    const __half *Ahp, *Alp, *Bhp, *Blp;
    if (mode == 0)      { Ahp = g_feath; Alp = g_featl; Bhp = g_w1h; Blp = g_w1l; }
    else if (mode == 1) { Ahp = g_fm1h;  Alp = g_fm1l;  Bhp = g_w2h; Blp = g_w2l; }
    else                { Ahp = g_fmh;   Alp = g_fml;   Bhp = g_wph; Blp = g_wpl; }

    const uint32_t* gsrc[4];
    gsrc[0] = (const uint32_t*)Ahp + (size_t)(bm * 64) * K2;
    gsrc[1] = (const uint32_t*)Alp + (size_t)(bm * 64) * K2;
    gsrc[2] = (const uint32_t*)Bhp + (size_t)(bn * 64) * K2;
    gsrc[3] = (const uint32_t*)Blp + (size_t)(bn * 64) * K2;

    if (mode == 2 && tid < 64) simg[tid] = bboxes[(bm * 64 + tid) * 5];

    const uint32_t sbase = smem_u32(&S[0][0][0][0]);

    float acc[2][4][4];
#pragma unroll
    for (int mt = 0; mt < 2; mt++)
#pragma unroll
        for (int nt = 0; nt < 4; nt++)
#pragma unroll
            for (int q = 0; q < 4; q++) acc[mt][nt][q] = 0.f;

    // ---- issue loads for one chunk (1024 x 16B across 128 threads) ----
    // id = tid + i*128; arr = i>>1; rem = tid + (i&1)*128; row = rem>>2; seg = rem&3
#define LOAD_CHUNK(ch, bf) do {                                              \
        int _kc2 = (ch) * 16;                                                \
        _Pragma("unroll")                                                    \
        for (int _i = 0; _i < 8; _i++) {                                     \
            int _arr = _i >> 1;                                              \
            int _rem = tid + (_i & 1) * 128;                                 \
            int _row = _rem >> 2, _seg = _rem & 3;                           \
            const uint32_t* _gp = gsrc[_arr] + (size_t)_row * K2 + _kc2 + _seg * 4; \
            uint32_t _dst = sbase +                                          \
                ((((bf) * 4 + _arr) * 64 + _row) * 20 + _seg * 4) * 4;       \
            CP_ASYNC16(_dst, _gp);                                           \
        }                                                                    \
    } while (0)

    LOAD_CHUNK(0, 0);
    CP_COMMIT();

    for (int c = 0; c < nch; c++) {
        const int buf = c & 1;
        if (c + 1 < nch) {
            LOAD_CHUNK(c + 1, buf ^ 1);
            CP_COMMIT();
            CP_WAIT(1);
        } else {
            CP_WAIT(0);
        }
        __syncthreads();

#pragma unroll
        for (int p = 0; p < 3; p++) {
            const uint32_t (*A)[20]  = S[buf][p == 1 ? 1 : 0];
            const uint32_t (*Bm)[20] = S[buf][p == 2 ? 3 : 2];
#pragma unroll
            for (int ks = 0; ks < 2; ks++) {
                const int k2o = ks * 8;
                uint32_t a[2][4];
#pragma unroll
                for (int mt = 0; mt < 2; mt++) {
                    int r = wm * 32 + mt * 16 + gid;
                    a[mt][0] = A[r][k2o + tig];
                    a[mt][1] = A[r + 8][k2o + tig];
                    a[mt][2] = A[r][k2o + tig + 4];
                    a[mt][3] = A[r + 8][k2o + tig + 4];
                }
#pragma unroll
                for (int nt = 0; nt < 4; nt++) {
                    int cn = wn * 32 + nt * 8 + gid;
                    uint32_t b0 = Bm[cn][k2o + tig];
                    uint32_t b1 = Bm[cn][k2o + tig + 4];
#pragma unroll
                    for (int mt = 0; mt < 2; mt++)
                        asm volatile(
                            "mma.sync.aligned.m16n8k16.row.col.f32.f16.f16.f32 "
                            "{%0,%1,%2,%3}, {%4,%5,%6,%7}, {%8,%9}, {%0,%1,%2,%3};"
                            : "+f"(acc[mt][nt][0]), "+f"(acc[mt][nt][1]),
                              "+f"(acc[mt][nt][2]), "+f"(acc[mt][nt][3])
                            : "r"(a[mt][0]), "r"(a[mt][1]), "r"(a[mt][2]),
                              "r"(a[mt][3]), "r"(b0), "r"(b1));
                }
            }
        }
        __syncthreads();
    }
#undef LOAD_CHUNK

    const int row0 = bm * 64 + wm * 32, col0 = bn * 64 + wn * 32;
    if (mode == 2) {
#pragma unroll
        for (int mt = 0; mt < 2; mt++) {
            int rl0 = wm * 32 + mt * 16 + gid, rl1 = rl0 + 8;
            int p0 = g_pos[bm * 64 + rl0], p1 = g_pos[bm * 64 + rl1];
            int im0 = simg[rl0], im1 = simg[rl1];
#pragma unroll
            for (int nt = 0; nt < 4; nt++) {
                int col = col0 + nt * 8 + tig * 2;
                if (p0 < MAXB) {
                    float* d = out_vis + ((size_t)im0 * MAXB + p0) * DD + col;
                    d[0] = acc[mt][nt][0] + g_hb[im0 * DD + col];
                    d[1] = acc[mt][nt][1] + g_hb[im0 * DD + col + 1];
                }
                if (p1 < MAXB) {
                    float* d = out_vis + ((size_t)im1 * MAXB + p1) * DD + col;
                    d[0] = acc[mt][nt][2] + g_hb[im1 * DD + col];
                    d[1] = acc[mt][nt][3] + g_hb[im1 * DD + col + 1];
                }
            }
        }
    } else {
        __half* oh = (mode == 0) ? g_fm1h : g_fmh;
        __half* ol = (mode == 0) ? g_fm1l : g_fml;
#pragma unroll
        for (int nt = 0; nt < 4; nt++) {
            int col = col0 + nt * 8 + tig * 2;
            float bv0 = bias[col], bv1 = bias[col + 1];
#pragma unroll
            for (int mt = 0; mt < 2; mt++) {
                int r = row0 + mt * 16 + gid;
                float v00 = acc[mt][nt][0] + bv0, v01 = acc[mt][nt][1] + bv1;
                float v10 = acc[mt][nt][2] + bv0, v11 = acc[mt][nt][3] + bv1;
                if (mode == 0) {
                    v00 = fmaxf(v00, 0.f); v01 = fmaxf(v01, 0.f);
                    v10 = fmaxf(v10, 0.f); v11 = fmaxf(v11, 0.f);
                }
                __half2 hp, lp;
                h2split(v00, &hp, &lp, v01);
                *(__half2*)&oh[(size_t)r * DD + col] = hp;
                *(__half2*)&ol[(size_t)r * DD + col] = lp;
                h2split(v10, &hp, &lp, v11);
                *(__half2*)&oh[(size_t)(r + 8) * DD + col] = hp;
                *(__half2*)&ol[(size_t)(r + 8) * DD + col] = lp;
            }
        }
    }
}

// ---------------- launch --------------------------------------------------------------
extern "C" void kernel_launch(void* const* d_in, const int* in_sizes, int n_in,
                              void* d_out, int out_size) {
    (void)in_sizes; (void)n_in; (void)out_size;
    const float* inputs   = (const float*)d_in[0];
    const int*   bboxes   = (const int*)  d_in[1];
    const float* features = (const float*)d_in[2];
    const float* t1w = (const float*)d_in[3],  *t1b = (const float*)d_in[4];
    const float* t2w = (const float*)d_in[5],  *t2b = (const float*)d_in[6];
    const float* d1w = (const float*)d_in[7],  *d1b = (const float*)d_in[8];
    const float* d2w = (const float*)d_in[9],  *d2b = (const float*)d_in[10];
    const float* m1w = (const float*)d_in[11], *m1b = (const float*)d_in[12];
    const float* m2w = (const float*)d_in[13], *m2b = (const float*)d_in[14];
    const float* pw  = (const float*)d_in[15], *pb  = (const float*)d_in[16];

    float* out      = (float*)d_out;
    float* out_vis  = out;
    float* out_mask = out + VIS_ELEMS;
    float* out_retx = out + VIS_ELEMS + MASK_ELEMS;

    conv_kernel<<<640, 256>>>(m1w, m2w, pw, features);             // 1
    mean_partial_kernel<<<BB * NC, 192>>>(inputs);                 // 2
    hgemm<<<dim3(16, 12), 128>>>(0, m1b, bboxes, nullptr);         // 3
    hgemm<<<dim3(16, 12), 128>>>(1, m2b, bboxes, nullptr);         // 4 <- profiled
    mean_final_kernel<<<12, 256>>>();                              // 5
    mlp_kernel<<<48, 256>>>(0, t1w, t1b, d1w, d1b, nullptr);       // 6
    mlp_kernel<<<48, 256>>>(1, t2w, t2b, d2w, d2b, out_retx);      // 7
    hb_kernel<<<24, 256>>>(pw, pb);                                // 8
    meta_kernel<<<1, NBOX>>>(bboxes, out_mask);                    // 9
    zero_vis_kernel<<<768, 256>>>((float4*)out_vis);               // 10
    hgemm<<<dim3(16, 12), 128>>>(2, nullptr, bboxes, out_vis);     // 11
}